// round 7
// baseline (speedup 1.0000x reference)
#include <cuda_runtime.h>

typedef unsigned long long u64;

// ---- packed f32x2 helpers (Blackwell sm_103a) ----
__device__ __forceinline__ u64 pk2(float a, float b) {
    u64 r; asm("mov.b64 %0,{%1,%2};" : "=l"(r) : "f"(a), "f"(b)); return r;
}
__device__ __forceinline__ void fma2(u64 &d, u64 a, u64 b) {
    asm("fma.rn.f32x2 %0,%1,%2,%0;" : "+l"(d) : "l"(a), "l"(b));
}
__device__ __forceinline__ u64 mul2(u64 a, u64 b) {
    u64 r; asm("mul.rn.f32x2 %0,%1,%2;" : "=l"(r) : "l"(a), "l"(b)); return r;
}
__device__ __forceinline__ u64 add2(u64 a, u64 b) {
    u64 r; asm("add.rn.f32x2 %0,%1,%2;" : "=l"(r) : "l"(a), "l"(b)); return r;
}
__device__ __forceinline__ void up2(u64 v, float &x, float &y) {
    asm("mov.b64 {%0,%1},%2;" : "=f"(x), "=f"(y) : "l"(v));
}
__device__ __forceinline__ void cp8(unsigned sa, const float2* ga) {
    asm volatile("cp.async.ca.shared.global [%0],[%1],8;" :: "r"(sa), "l"(ga));
}
__device__ __forceinline__ void cp_commit() {
    asm volatile("cp.async.commit_group;");
}
__device__ __forceinline__ void cp_wait2() {
    asm volatile("cp.async.wait_group 2;");
}

// Shapes: x:(64,4,2,256,256) w:(4,4,128,128,16,2) bias:(4,128,128,2) out:(64,4,2,128,128)
#define NCHUNK 2
#define NPC (64 / NCHUNK)     // 32 n per block
#define XBUF 128              // float2 per x slice: 4(ir) * 4c * 8y

// Block = 128 threads = 4 warps, 6 blocks/SM (6 independent barrier domains).
//   warp w owns output channel p = w; lane = c*8 + dy; y = y0 + dy (y-tile of 8).
// Grid = 128 (x) * 16 (y-tile) * NCHUNK = 4096.
// x pipelined via cp.async 4-buffer ring, depth 3, ONE sync per slice.
__global__ void __launch_bounds__(128, 6) ttn_kernel(
    const float* __restrict__ X, const float* __restrict__ W,
    const float* __restrict__ B, float* __restrict__ O)
{
    __shared__ __align__(16) float4 smw[256];          // 4 KB weight staging
    __shared__ __align__(16) float2 xsm[4 * XBUF];     // 4 KB x ring

    const int tid  = threadIdx.x;
    const int warp = tid >> 5;     // = p
    const int lane = tid & 31;
    const int c    = lane >> 3;
    const int dy   = lane & 7;

    const int bid = blockIdx.x;
    const int nch = bid >> 11;
    const int rem = bid & 2047;
    const int xp  = rem >> 4;
    const int y0  = (rem & 15) * 8;
    const int n0  = nch * NPC;

    // ---- x staging: identity map, 1 float2 per thread per slice ----
    // tid -> ir = tid>>5 (i=ir>>1, r=ir&1), c_ = (tid>>3)&3, yy = tid&7
    const int ir_ = tid >> 5, c_ = (tid >> 3) & 3, yy_ = tid & 7;
    const int i_ = ir_ >> 1, r_ = ir_ & 1;
    const float2* Xf2 = (const float2*)X;
    const int goff = (c_ * 2 + i_) * 32768 + (2 * xp + r_) * 128 + y0 + yy_;

    unsigned sbase = (unsigned)__cvta_generic_to_shared(xsm);
    unsigned sa    = sbase + (unsigned)tid * 8u;

    // prologue: cp.async slices 0,1,2 (overlapped with weight staging)
#pragma unroll
    for (int s = 0; s < 3; ++s) {
        cp8(sa + (unsigned)s * XBUF * 8u, Xf2 + (long)(n0 + s) * 262144 + goff);
        cp_commit();
    }

    // ---- stage weights gmem -> smem (coalesced) -> registers (swizzled) ----
    // per round r (= c value): [p(4)][yy(8)][j(8)] float4, p-aware XOR swizzle
    u64 w2[16];
    for (int r = 0; r < 4; ++r) {
        __syncthreads();
#pragma unroll
        for (int k = 0; k < 2; ++k) {
            int G  = k * 128 + tid;        // 0..255
            int p  = G >> 6;
            int yy = (G >> 3) & 7;
            int j  = G & 7;
            float4 v = __ldg((const float4*)W +
                             (((r * 4 + p) * 16384 + xp * 128 + y0 + yy) * 8 + j));
            smw[p * 64 + yy * 8 + (j ^ yy ^ (p << 1))] = v;
        }
        __syncthreads();
        if (c == r) {
#pragma unroll
            for (int t = 0; t < 8; ++t) {
                float4 v = smw[warp * 64 + dy * 8 + (t ^ dy ^ (warp << 1))];
                w2[2 * t]     = pk2(v.x, v.y);
                w2[2 * t + 1] = pk2(v.z, v.w);
            }
        }
    }

    // bias pair for (p=warp, xp, y0+dy) — used by c==0 lanes
    const float2 bz = *(const float2*)(B + ((warp * 128 + xp) * 128 + y0 + dy) * 2);

    const int OSTR  = 4 * 2 * 16384;
    const int obase = ((n0 * 4 + warp) * 2) * 16384 + xp * 128 + y0 + dy;

#pragma unroll 4
    for (int s = 0; s < NPC; ++s) {
        cp_wait2();          // group for slice s has landed
        __syncthreads();     // visible to all; also retires last iter's reads

        const float2* buf = xsm + (s & 3) * XBUF;
        float2 A0 = buf[lane];        // (a0,e0)  i=0,r=0
        float2 A1 = buf[32 + lane];   // (b0,f0)  i=0,r=1
        float2 A2 = buf[64 + lane];   // (a1,e1)  i=1,r=0
        float2 A3 = buf[96 + lane];   // (b1,f1)  i=1,r=1

        // refill slice s+3 into the buffer consumed in iter s-1
        if (s + 3 < NPC) {
            cp8(sa + (unsigned)((s + 3) & 3) * XBUF * 8u,
                Xf2 + (long)(n0 + s + 3) * 262144 + goff);
        }
        cp_commit();

        const float a0 = A0.x, e0 = A0.y, b0 = A1.x, f0 = A1.y;
        const float a1 = A2.x, e1 = A2.y, b1 = A3.x, f1 = A3.y;

        u64 ab2[4] = { pk2(a0*b0,a0*b0), pk2(a0*b1,a0*b1),
                       pk2(a1*b0,a1*b0), pk2(a1*b1,a1*b1) };
        u64 ef2[4] = { pk2(e0*f0,e0*f0), pk2(e0*f1,e0*f1),
                       pk2(e1*f0,e1*f0), pk2(e1*f1,e1*f1) };

        // acc = sum_g ab[g] * (sum_m w2[g*4+m] * ef[m])   (p = warp fixed)
        u64 acc;
#pragma unroll
        for (int g = 0; g < 4; ++g) {
            u64 t0 = mul2(w2[g*4+0], ef2[0]);
            fma2(t0, w2[g*4+1], ef2[1]);
            fma2(t0, w2[g*4+2], ef2[2]);
            fma2(t0, w2[g*4+3], ef2[3]);
            if (g == 0) acc = mul2(ab2[0], t0);
            else        fma2(acc, ab2[g], t0);
        }

        // reduce over c (lane bits 3,4): butterfly xor 8 then xor 16
        acc = add2(acc, __shfl_xor_sync(0xffffffffu, acc, 8));
        acc = add2(acc, __shfl_xor_sync(0xffffffffu, acc, 16));

        if (c == 0) {
            float r0, r1; up2(acc, r0, r1);
            int oo = obase + s * OSTR;
            O[oo]         = r0 + bz.x;
            O[oo + 16384] = r1 + bz.y;
        }
    }
}

extern "C" void kernel_launch(void* const* d_in, const int* in_sizes, int n_in,
                              void* d_out, int out_size)
{
    const float* X = (const float*)d_in[0];   // x        (64,4,2,256,256)
    const float* W = (const float*)d_in[1];   // tensors  (4,4,128,128,2,2,2,2,2)
    const float* B = (const float*)d_in[2];   // bias     (4,128,128,2)
    float* O = (float*)d_out;                 // out      (64,4,2,128,128)
    (void)in_sizes; (void)n_in; (void)out_size;
    ttn_kernel<<<128 * 16 * NCHUNK, 128>>>(X, W, B, O);
}

// round 8
// speedup vs baseline: 1.1028x; 1.1028x over previous
#include <cuda_runtime.h>

typedef unsigned long long u64;

// ---- packed f32x2 helpers (Blackwell sm_103a) ----
__device__ __forceinline__ u64 pk2(float a, float b) {
    u64 r; asm("mov.b64 %0,{%1,%2};" : "=l"(r) : "f"(a), "f"(b)); return r;
}
__device__ __forceinline__ void fma2(u64 &d, u64 a, u64 b) {
    asm("fma.rn.f32x2 %0,%1,%2,%0;" : "+l"(d) : "l"(a), "l"(b));
}
__device__ __forceinline__ u64 mul2(u64 a, u64 b) {
    u64 r; asm("mul.rn.f32x2 %0,%1,%2;" : "=l"(r) : "l"(a), "l"(b)); return r;
}
__device__ __forceinline__ u64 add2(u64 a, u64 b) {
    u64 r; asm("add.rn.f32x2 %0,%1,%2;" : "=l"(r) : "l"(a), "l"(b)); return r;
}
__device__ __forceinline__ void up2(u64 v, float &x, float &y) {
    asm("mov.b64 {%0,%1},%2;" : "=f"(x), "=f"(y) : "l"(v));
}
__device__ __forceinline__ void cp8(unsigned sa, const float2* ga) {
    asm volatile("cp.async.ca.shared.global [%0],[%1],8;" :: "r"(sa), "l"(ga));
}
__device__ __forceinline__ void cp_commit() {
    asm volatile("cp.async.commit_group;");
}
__device__ __forceinline__ void cp_wait1() {
    asm volatile("cp.async.wait_group 1;");
}

// Shapes: x:(64,4,2,256,256) w:(4,4,128,128,16,2) bias:(4,128,128,2) out:(64,4,2,128,128)
#define NPC 64                // all n per block (weights read from DRAM once)
#define XBUF 128              // float2 per x slice: 4(ir) * 4c * 8y = 1 KB
#define NBUF 6                // ring depth (slices), 6 KB

// Block = 128 threads = 4 warps, 5 blocks/SM (5 independent barrier domains).
//   warp w owns output channel p = w; lane = c*8 + dy; y = y0 + dy (y-tile of 8).
// Grid = 128 (x) * 16 (y-tile) = 2048.
// x pipelined via cp.async 6-buffer ring; TWO n-slices per barrier window
// (one __syncthreads per 2 slices), 2-slice commit groups, wait_group 1.
__global__ void __launch_bounds__(128, 5) ttn_kernel(
    const float* __restrict__ X, const float* __restrict__ W,
    const float* __restrict__ B, float* __restrict__ O)
{
    __shared__ __align__(16) float4 smw[256];            // 4 KB weight staging
    __shared__ __align__(16) float2 xsm[NBUF * XBUF];    // 6 KB x ring

    const int tid  = threadIdx.x;
    const int warp = tid >> 5;     // = p
    const int lane = tid & 31;
    const int c    = lane >> 3;
    const int dy   = lane & 7;

    const int bid = blockIdx.x;
    const int xp  = bid >> 4;
    const int y0  = (bid & 15) * 8;

    // ---- x staging: identity map, 1 float2 per thread per slice ----
    const int ir_ = tid >> 5, c_ = (tid >> 3) & 3, yy_ = tid & 7;
    const int i_ = ir_ >> 1, r_ = ir_ & 1;
    const float2* Xf2 = (const float2*)X;
    const int goff = (c_ * 2 + i_) * 32768 + (2 * xp + r_) * 128 + y0 + yy_;

    unsigned sbase = (unsigned)__cvta_generic_to_shared(xsm);
    unsigned sa    = sbase + (unsigned)tid * 8u;

    // prologue: slices 0..3 as two 2-slice groups (overlap weight staging)
    cp8(sa + 0u * XBUF * 8u, Xf2 + 0L * 262144 + goff);
    cp8(sa + 1u * XBUF * 8u, Xf2 + 1L * 262144 + goff);
    cp_commit();
    cp8(sa + 2u * XBUF * 8u, Xf2 + 2L * 262144 + goff);
    cp8(sa + 3u * XBUF * 8u, Xf2 + 3L * 262144 + goff);
    cp_commit();

    // ---- stage weights gmem -> smem (coalesced) -> registers (swizzled) ----
    u64 w2[16];
    for (int r = 0; r < 4; ++r) {
        __syncthreads();
#pragma unroll
        for (int k = 0; k < 2; ++k) {
            int G  = k * 128 + tid;        // 0..255
            int p  = G >> 6;
            int yy = (G >> 3) & 7;
            int j  = G & 7;
            float4 v = __ldg((const float4*)W +
                             (((r * 4 + p) * 16384 + xp * 128 + y0 + yy) * 8 + j));
            smw[p * 64 + yy * 8 + (j ^ yy ^ (p << 1))] = v;
        }
        __syncthreads();
        if (c == r) {
#pragma unroll
            for (int t = 0; t < 8; ++t) {
                float4 v = smw[warp * 64 + dy * 8 + (t ^ dy ^ (warp << 1))];
                w2[2 * t]     = pk2(v.x, v.y);
                w2[2 * t + 1] = pk2(v.z, v.w);
            }
        }
    }

    const float2 bz = *(const float2*)(B + ((warp * 128 + xp) * 128 + y0 + dy) * 2);
    const int OSTR  = 4 * 2 * 16384;
    const int obase = (warp * 2) * 16384 + xp * 128 + y0 + dy;

#pragma unroll 3
    for (int w = 0; w < NPC / 2; ++w) {
        const int sA = 2 * w, sB = 2 * w + 1;
        cp_wait1();          // group holding slices sA,sB has landed
        __syncthreads();     // visible; also retires window w-1's reads

        const float2* bufA = xsm + (sA % NBUF) * XBUF;
        const float2* bufB = xsm + (sB % NBUF) * XBUF;
        float2 A0 = bufA[lane],      A1 = bufA[32 + lane];
        float2 A2 = bufA[64 + lane], A3 = bufA[96 + lane];
        float2 B0 = bufB[lane],      B1 = bufB[32 + lane];
        float2 B2 = bufB[64 + lane], B3 = bufB[96 + lane];

        // refill slices sA+4, sB+4 (targets differ from this window's buffers)
        if (sA + 4 < NPC) {
            cp8(sa + (unsigned)((sA + 4) % NBUF) * XBUF * 8u,
                Xf2 + (long)(sA + 4) * 262144 + goff);
            cp8(sa + (unsigned)((sB + 4) % NBUF) * XBUF * 8u,
                Xf2 + (long)(sB + 4) * 262144 + goff);
        }
        cp_commit();

        u64 accA, accB;
        {
            const float a0 = A0.x, e0 = A0.y, b0 = A1.x, f0 = A1.y;
            const float a1 = A2.x, e1 = A2.y, b1 = A3.x, f1 = A3.y;
            u64 ab2[4] = { pk2(a0*b0,a0*b0), pk2(a0*b1,a0*b1),
                           pk2(a1*b0,a1*b0), pk2(a1*b1,a1*b1) };
            u64 ef2[4] = { pk2(e0*f0,e0*f0), pk2(e0*f1,e0*f1),
                           pk2(e1*f0,e1*f0), pk2(e1*f1,e1*f1) };
#pragma unroll
            for (int g = 0; g < 4; ++g) {
                u64 t0 = mul2(w2[g*4+0], ef2[0]);
                fma2(t0, w2[g*4+1], ef2[1]);
                fma2(t0, w2[g*4+2], ef2[2]);
                fma2(t0, w2[g*4+3], ef2[3]);
                if (g == 0) accA = mul2(ab2[0], t0);
                else        fma2(accA, ab2[g], t0);
            }
        }
        {
            const float a0 = B0.x, e0 = B0.y, b0 = B1.x, f0 = B1.y;
            const float a1 = B2.x, e1 = B2.y, b1 = B3.x, f1 = B3.y;
            u64 ab2[4] = { pk2(a0*b0,a0*b0), pk2(a0*b1,a0*b1),
                           pk2(a1*b0,a1*b0), pk2(a1*b1,a1*b1) };
            u64 ef2[4] = { pk2(e0*f0,e0*f0), pk2(e0*f1,e0*f1),
                           pk2(e1*f0,e1*f0), pk2(e1*f1,e1*f1) };
#pragma unroll
            for (int g = 0; g < 4; ++g) {
                u64 t0 = mul2(w2[g*4+0], ef2[0]);
                fma2(t0, w2[g*4+1], ef2[1]);
                fma2(t0, w2[g*4+2], ef2[2]);
                fma2(t0, w2[g*4+3], ef2[3]);
                if (g == 0) accB = mul2(ab2[0], t0);
                else        fma2(accB, ab2[g], t0);
            }
        }

        // reduce over c (two independent butterfly chains)
        accA = add2(accA, __shfl_xor_sync(0xffffffffu, accA, 8));
        accB = add2(accB, __shfl_xor_sync(0xffffffffu, accB, 8));
        accA = add2(accA, __shfl_xor_sync(0xffffffffu, accA, 16));
        accB = add2(accB, __shfl_xor_sync(0xffffffffu, accB, 16));

        if (c == 0) {
            float r0, r1; up2(accA, r0, r1);
            float s0, s1; up2(accB, s0, s1);
            int oA = obase + sA * OSTR;
            int oB = obase + sB * OSTR;
            O[oA]         = r0 + bz.x;
            O[oA + 16384] = r1 + bz.y;
            O[oB]         = s0 + bz.x;
            O[oB + 16384] = s1 + bz.y;
        }
    }
}

extern "C" void kernel_launch(void* const* d_in, const int* in_sizes, int n_in,
                              void* d_out, int out_size)
{
    const float* X = (const float*)d_in[0];   // x        (64,4,2,256,256)
    const float* W = (const float*)d_in[1];   // tensors  (4,4,128,128,2,2,2,2,2)
    const float* B = (const float*)d_in[2];   // bias     (4,128,128,2)
    float* O = (float*)d_out;                 // out      (64,4,2,128,128)
    (void)in_sizes; (void)n_in; (void)out_size;
    ttn_kernel<<<128 * 16, 128>>>(X, W, B, O);
}

// round 9
// speedup vs baseline: 1.2370x; 1.1217x over previous
#include <cuda_runtime.h>

typedef unsigned long long u64;

// ---- packed f32x2 helpers (Blackwell sm_103a) ----
__device__ __forceinline__ u64 pk2(float a, float b) {
    u64 r; asm("mov.b64 %0,{%1,%2};" : "=l"(r) : "f"(a), "f"(b)); return r;
}
__device__ __forceinline__ void fma2(u64 &d, u64 a, u64 b) {
    asm("fma.rn.f32x2 %0,%1,%2,%0;" : "+l"(d) : "l"(a), "l"(b));
}
__device__ __forceinline__ u64 mul2(u64 a, u64 b) {
    u64 r; asm("mul.rn.f32x2 %0,%1,%2;" : "=l"(r) : "l"(a), "l"(b)); return r;
}
__device__ __forceinline__ u64 add2(u64 a, u64 b) {
    u64 r; asm("add.rn.f32x2 %0,%1,%2;" : "=l"(r) : "l"(a), "l"(b)); return r;
}
__device__ __forceinline__ void up2(u64 v, float &x, float &y) {
    asm("mov.b64 {%0,%1},%2;" : "=f"(x), "=f"(y) : "l"(v));
}
__device__ __forceinline__ void cp8(unsigned sa, const float2* ga) {
    asm volatile("cp.async.ca.shared.global [%0],[%1],8;" :: "r"(sa), "l"(ga));
}
__device__ __forceinline__ void cp_commit() {
    asm volatile("cp.async.commit_group;");
}
__device__ __forceinline__ void cp_wait1() {
    asm volatile("cp.async.wait_group 1;");
}

// Shapes: x:(64,4,2,256,256) w:(4,4,128,128,16,2) bias:(4,128,128,2) out:(64,4,2,128,128)
#define NPC 64                // all n per block (weights read from DRAM once)
#define XBUF 128              // float2 per x slice: 4(ir) * 4c * 8y = 1 KB
#define NBUF 12               // ring depth (slices), 12 KB

// Block = 128 threads = 4 warps, 5 blocks/SM (5 independent barrier domains).
//   warp w owns output channel p = w; lane = c*8 + dy; y = y0 + dy (y-tile of 8).
// Grid = 128 (x) * 16 (y-tile) = 2048.
// x pipelined via cp.async 12-buffer ring; FOUR n-slices per barrier window:
// one __syncthreads + one wait per 4 slices. Refill (slices s+8) targets buffers
// disjoint from windows w and w+1, so it is issued right after the sync.
__global__ void __launch_bounds__(128, 5) ttn_kernel(
    const float* __restrict__ X, const float* __restrict__ W,
    const float* __restrict__ B, float* __restrict__ O)
{
    __shared__ __align__(16) float4 smw[256];            // 4 KB weight staging
    __shared__ __align__(16) float2 xsm[NBUF * XBUF];    // 12 KB x ring

    const int tid  = threadIdx.x;
    const int warp = tid >> 5;     // = p
    const int lane = tid & 31;
    const int c    = lane >> 3;
    const int dy   = lane & 7;

    const int bid = blockIdx.x;
    const int xp  = bid >> 4;
    const int y0  = (bid & 15) * 8;

    // ---- x staging: identity map, 1 float2 per thread per slice ----
    const int ir_ = tid >> 5, c_ = (tid >> 3) & 3, yy_ = tid & 7;
    const int i_ = ir_ >> 1, r_ = ir_ & 1;
    const float2* Xf2 = (const float2*)X;
    const int goff = (c_ * 2 + i_) * 32768 + (2 * xp + r_) * 128 + y0 + yy_;

    unsigned sbase = (unsigned)__cvta_generic_to_shared(xsm);
    unsigned sa    = sbase + (unsigned)tid * 8u;

    // prologue: windows 0 and 1 (slices 0..7) as two 4-slice groups
#pragma unroll
    for (int s = 0; s < 4; ++s)
        cp8(sa + (unsigned)s * XBUF * 8u, Xf2 + (long)s * 262144 + goff);
    cp_commit();
#pragma unroll
    for (int s = 4; s < 8; ++s)
        cp8(sa + (unsigned)s * XBUF * 8u, Xf2 + (long)s * 262144 + goff);
    cp_commit();

    // ---- stage weights gmem -> smem (coalesced) -> registers (swizzled) ----
    u64 w2[16];
    for (int r = 0; r < 4; ++r) {
        __syncthreads();
#pragma unroll
        for (int k = 0; k < 2; ++k) {
            int G  = k * 128 + tid;        // 0..255
            int p  = G >> 6;
            int yy = (G >> 3) & 7;
            int j  = G & 7;
            float4 v = __ldg((const float4*)W +
                             (((r * 4 + p) * 16384 + xp * 128 + y0 + yy) * 8 + j));
            smw[p * 64 + yy * 8 + (j ^ yy ^ (p << 1))] = v;
        }
        __syncthreads();
        if (c == r) {
#pragma unroll
            for (int t = 0; t < 8; ++t) {
                float4 v = smw[warp * 64 + dy * 8 + (t ^ dy ^ (warp << 1))];
                w2[2 * t]     = pk2(v.x, v.y);
                w2[2 * t + 1] = pk2(v.z, v.w);
            }
        }
    }

    const float2 bz = *(const float2*)(B + ((warp * 128 + xp) * 128 + y0 + dy) * 2);
    const int OSTR  = 4 * 2 * 16384;
    int oo = (warp * 2) * 16384 + xp * 128 + y0 + dy;   // advances by OSTR per slice

    int rb  = 0;    // ring buffer base of current window ((4w) % 12)
    int rb2 = 8;    // ring buffer base of refill target ((4w+8) % 12)

    for (int w = 0; w < NPC / 4; ++w) {
        const int s0 = 4 * w;
        cp_wait1();          // group holding slices s0..s0+3 has landed
        __syncthreads();     // visible; retires window w-1's reads

        // refill slices s0+8..s0+11 into buffers rb2.. (disjoint from w, w+1)
        if (s0 + 8 < NPC) {
#pragma unroll
            for (int j = 0; j < 4; ++j)
                cp8(sa + (unsigned)(rb2 + j) * XBUF * 8u,
                    Xf2 + (long)(s0 + 8 + j) * 262144 + goff);
        }
        cp_commit();

        // two sub-pairs of slices; register-light
#pragma unroll
        for (int h = 0; h < 2; ++h) {
            const float2* bufA = xsm + (rb + 2 * h)     * XBUF;
            const float2* bufB = xsm + (rb + 2 * h + 1) * XBUF;
            float2 A0 = bufA[lane],      A1 = bufA[32 + lane];
            float2 A2 = bufA[64 + lane], A3 = bufA[96 + lane];
            float2 B0 = bufB[lane],      B1 = bufB[32 + lane];
            float2 B2 = bufB[64 + lane], B3 = bufB[96 + lane];

            u64 accA, accB;
            {
                const float a0 = A0.x, e0 = A0.y, b0 = A1.x, f0 = A1.y;
                const float a1 = A2.x, e1 = A2.y, b1 = A3.x, f1 = A3.y;
                u64 ab2[4] = { pk2(a0*b0,a0*b0), pk2(a0*b1,a0*b1),
                               pk2(a1*b0,a1*b0), pk2(a1*b1,a1*b1) };
                u64 ef2[4] = { pk2(e0*f0,e0*f0), pk2(e0*f1,e0*f1),
                               pk2(e1*f0,e1*f0), pk2(e1*f1,e1*f1) };
#pragma unroll
                for (int g = 0; g < 4; ++g) {
                    u64 t0 = mul2(w2[g*4+0], ef2[0]);
                    fma2(t0, w2[g*4+1], ef2[1]);
                    fma2(t0, w2[g*4+2], ef2[2]);
                    fma2(t0, w2[g*4+3], ef2[3]);
                    if (g == 0) accA = mul2(ab2[0], t0);
                    else        fma2(accA, ab2[g], t0);
                }
            }
            {
                const float a0 = B0.x, e0 = B0.y, b0 = B1.x, f0 = B1.y;
                const float a1 = B2.x, e1 = B2.y, b1 = B3.x, f1 = B3.y;
                u64 ab2[4] = { pk2(a0*b0,a0*b0), pk2(a0*b1,a0*b1),
                               pk2(a1*b0,a1*b0), pk2(a1*b1,a1*b1) };
                u64 ef2[4] = { pk2(e0*f0,e0*f0), pk2(e0*f1,e0*f1),
                               pk2(e1*f0,e1*f0), pk2(e1*f1,e1*f1) };
#pragma unroll
                for (int g = 0; g < 4; ++g) {
                    u64 t0 = mul2(w2[g*4+0], ef2[0]);
                    fma2(t0, w2[g*4+1], ef2[1]);
                    fma2(t0, w2[g*4+2], ef2[2]);
                    fma2(t0, w2[g*4+3], ef2[3]);
                    if (g == 0) accB = mul2(ab2[0], t0);
                    else        fma2(accB, ab2[g], t0);
                }
            }

            accA = add2(accA, __shfl_xor_sync(0xffffffffu, accA, 8));
            accB = add2(accB, __shfl_xor_sync(0xffffffffu, accB, 8));
            accA = add2(accA, __shfl_xor_sync(0xffffffffu, accA, 16));
            accB = add2(accB, __shfl_xor_sync(0xffffffffu, accB, 16));

            if (c == 0) {
                float r0, r1; up2(accA, r0, r1);
                float s0v, s1v; up2(accB, s0v, s1v);
                O[oo]                 = r0  + bz.x;
                O[oo + 16384]         = r1  + bz.y;
                O[oo + OSTR]          = s0v + bz.x;
                O[oo + OSTR + 16384]  = s1v + bz.y;
            }
            oo += 2 * OSTR;
        }

        rb  = (rb  == 8) ? 0 : rb  + 4;
        rb2 = (rb2 == 8) ? 0 : rb2 + 4;
    }
}

extern "C" void kernel_launch(void* const* d_in, const int* in_sizes, int n_in,
                              void* d_out, int out_size)
{
    const float* X = (const float*)d_in[0];   // x        (64,4,2,256,256)
    const float* W = (const float*)d_in[1];   // tensors  (4,4,128,128,2,2,2,2,2)
    const float* B = (const float*)d_in[2];   // bias     (4,128,128,2)
    float* O = (float*)d_out;                 // out      (64,4,2,128,128)
    (void)in_sizes; (void)n_in; (void)out_size;
    ttn_kernel<<<128 * 16, 128>>>(X, W, B, O);
}

// round 10
// speedup vs baseline: 1.2716x; 1.0280x over previous
#include <cuda_runtime.h>

typedef unsigned long long u64;

// ---- packed f32x2 helpers (Blackwell sm_103a) ----
__device__ __forceinline__ u64 pk2(float a, float b) {
    u64 r; asm("mov.b64 %0,{%1,%2};" : "=l"(r) : "f"(a), "f"(b)); return r;
}
__device__ __forceinline__ void fma2(u64 &d, u64 a, u64 b) {
    asm("fma.rn.f32x2 %0,%1,%2,%0;" : "+l"(d) : "l"(a), "l"(b));
}
__device__ __forceinline__ u64 mul2(u64 a, u64 b) {
    u64 r; asm("mul.rn.f32x2 %0,%1,%2;" : "=l"(r) : "l"(a), "l"(b)); return r;
}
__device__ __forceinline__ u64 add2(u64 a, u64 b) {
    u64 r; asm("add.rn.f32x2 %0,%1,%2;" : "=l"(r) : "l"(a), "l"(b)); return r;
}
__device__ __forceinline__ void up2(u64 v, float &x, float &y) {
    asm("mov.b64 {%0,%1},%2;" : "=f"(x), "=f"(y) : "l"(v));
}
__device__ __forceinline__ void cp8(unsigned sa, const float2* ga) {
    asm volatile("cp.async.ca.shared.global [%0],[%1],8;" :: "r"(sa), "l"(ga));
}
__device__ __forceinline__ void cp_commit() {
    asm volatile("cp.async.commit_group;");
}
__device__ __forceinline__ void cp_wait1() {
    asm volatile("cp.async.wait_group 1;");
}

// Shapes: x:(64,4,2,256,256) w:(4,4,128,128,16,2) bias:(4,128,128,2) out:(64,4,2,128,128)
#define NPC 64                // all n per block (weights read from DRAM once)
#define XBUF 128              // float2 per x slice: 4(ir) * 4c * 8y = 1 KB
#define NBUF 12               // ring depth (slices), 12 KB
#define NSTR 262144           // per-n stride in x, float2 units

// Block = 128 threads = 4 warps, 6 blocks/SM (6 independent barrier domains).
//   warp w owns output channel p = w; lane = c*8 + dy; y = y0 + dy (y-tile of 8).
// Grid = 128 (x) * 16 (y-tile) = 2048.
// x pipelined via cp.async 12-buffer ring; FOUR n-slices per barrier window.
__global__ void __launch_bounds__(128, 6) ttn_kernel(
    const float* __restrict__ X, const float* __restrict__ W,
    const float* __restrict__ B, float* __restrict__ O)
{
    __shared__ __align__(16) float4 smw[256];            // 4 KB weight staging
    __shared__ __align__(16) float2 xsm[NBUF * XBUF];    // 12 KB x ring

    const int tid  = threadIdx.x;
    const int warp = tid >> 5;     // = p
    const int lane = tid & 31;
    const int c    = lane >> 3;
    const int dy   = lane & 7;

    const int bid = blockIdx.x;
    const int xp  = bid >> 4;
    const int y0  = (bid & 15) * 8;

    // ---- x staging: identity map, 1 float2 per thread per slice ----
    const int ir_ = tid >> 5, c_ = (tid >> 3) & 3, yy_ = tid & 7;
    const int i_ = ir_ >> 1, r_ = ir_ & 1;
    const int goff = (c_ * 2 + i_) * 32768 + (2 * xp + r_) * 128 + y0 + yy_;

    unsigned sbase = (unsigned)__cvta_generic_to_shared(xsm);
    unsigned sa    = sbase + (unsigned)tid * 8u;

    // prologue: windows 0 and 1 (slices 0..7) as two 4-slice groups
    {
        const float2* gp = (const float2*)X + goff;
#pragma unroll
        for (int s = 0; s < 4; ++s)
            cp8(sa + (unsigned)s * XBUF * 8u, gp + (long)s * NSTR);
        cp_commit();
#pragma unroll
        for (int s = 4; s < 8; ++s)
            cp8(sa + (unsigned)s * XBUF * 8u, gp + (long)s * NSTR);
        cp_commit();
    }

    // ---- stage weights gmem -> smem (coalesced) -> registers (swizzled) ----
    u64 w2[16];
    for (int r = 0; r < 4; ++r) {
        __syncthreads();
#pragma unroll
        for (int k = 0; k < 2; ++k) {
            int G  = k * 128 + tid;        // 0..255
            int p  = G >> 6;
            int yy = (G >> 3) & 7;
            int j  = G & 7;
            float4 v = __ldg((const float4*)W +
                             (((r * 4 + p) * 16384 + xp * 128 + y0 + yy) * 8 + j));
            smw[p * 64 + yy * 8 + (j ^ yy ^ (p << 1))] = v;
        }
        __syncthreads();
        if (c == r) {
#pragma unroll
            for (int t = 0; t < 8; ++t) {
                float4 v = smw[warp * 64 + dy * 8 + (t ^ dy ^ (warp << 1))];
                w2[2 * t]     = pk2(v.x, v.y);
                w2[2 * t + 1] = pk2(v.z, v.w);
            }
        }
    }

    const float2 bz = *(const float2*)(B + ((warp * 128 + xp) * 128 + y0 + dy) * 2);
    const int OSTR = 4 * 2 * 16384;
    int oo = (warp * 2) * 16384 + xp * 128 + y0 + dy;   // advances per slice

    // moving refill pointer: window w refills slices 4w+8..4w+11
    const float2* gref = (const float2*)X + goff + 8L * NSTR;

    int rb  = 0;    // ring base of current window ((4w) % 12)
    int rb2 = 8;    // ring base of refill target ((4w+8) % 12)

#pragma unroll 3
    for (int w = 0; w < NPC / 4; ++w) {
        cp_wait1();          // group holding this window's slices has landed
        __syncthreads();     // visible; retires window w-1's reads

        // refill 4 slices into buffers rb2.. (disjoint from windows w, w+1)
        if (w < NPC / 4 - 2) {
#pragma unroll
            for (int j = 0; j < 4; ++j)
                cp8(sa + (unsigned)(rb2 + j) * XBUF * 8u, gref + (long)j * NSTR);
        }
        cp_commit();
        gref += 4L * NSTR;

        // two sub-pairs of slices; register-light
#pragma unroll
        for (int h = 0; h < 2; ++h) {
            const float2* bufA = xsm + (rb + 2 * h)     * XBUF;
            const float2* bufB = xsm + (rb + 2 * h + 1) * XBUF;
            float2 A0 = bufA[lane],      A1 = bufA[32 + lane];
            float2 A2 = bufA[64 + lane], A3 = bufA[96 + lane];
            float2 B0 = bufB[lane],      B1 = bufB[32 + lane];
            float2 B2 = bufB[64 + lane], B3 = bufB[96 + lane];

            u64 accA, accB;
            {
                const float a0 = A0.x, e0 = A0.y, b0 = A1.x, f0 = A1.y;
                const float a1 = A2.x, e1 = A2.y, b1 = A3.x, f1 = A3.y;
                u64 ab2[4] = { pk2(a0*b0,a0*b0), pk2(a0*b1,a0*b1),
                               pk2(a1*b0,a1*b0), pk2(a1*b1,a1*b1) };
                u64 ef2[4] = { pk2(e0*f0,e0*f0), pk2(e0*f1,e0*f1),
                               pk2(e1*f0,e1*f0), pk2(e1*f1,e1*f1) };
#pragma unroll
                for (int g = 0; g < 4; ++g) {
                    u64 t0 = mul2(w2[g*4+0], ef2[0]);
                    fma2(t0, w2[g*4+1], ef2[1]);
                    fma2(t0, w2[g*4+2], ef2[2]);
                    fma2(t0, w2[g*4+3], ef2[3]);
                    if (g == 0) accA = mul2(ab2[0], t0);
                    else        fma2(accA, ab2[g], t0);
                }
            }
            {
                const float a0 = B0.x, e0 = B0.y, b0 = B1.x, f0 = B1.y;
                const float a1 = B2.x, e1 = B2.y, b1 = B3.x, f1 = B3.y;
                u64 ab2[4] = { pk2(a0*b0,a0*b0), pk2(a0*b1,a0*b1),
                               pk2(a1*b0,a1*b0), pk2(a1*b1,a1*b1) };
                u64 ef2[4] = { pk2(e0*f0,e0*f0), pk2(e0*f1,e0*f1),
                               pk2(e1*f0,e1*f0), pk2(e1*f1,e1*f1) };
#pragma unroll
                for (int g = 0; g < 4; ++g) {
                    u64 t0 = mul2(w2[g*4+0], ef2[0]);
                    fma2(t0, w2[g*4+1], ef2[1]);
                    fma2(t0, w2[g*4+2], ef2[2]);
                    fma2(t0, w2[g*4+3], ef2[3]);
                    if (g == 0) accB = mul2(ab2[0], t0);
                    else        fma2(accB, ab2[g], t0);
                }
            }

            accA = add2(accA, __shfl_xor_sync(0xffffffffu, accA, 8));
            accB = add2(accB, __shfl_xor_sync(0xffffffffu, accB, 8));
            accA = add2(accA, __shfl_xor_sync(0xffffffffu, accA, 16));
            accB = add2(accB, __shfl_xor_sync(0xffffffffu, accB, 16));

            if (c == 0) {
                float r0, r1; up2(accA, r0, r1);
                float s0v, s1v; up2(accB, s0v, s1v);
                O[oo]                 = r0  + bz.x;
                O[oo + 16384]         = r1  + bz.y;
                O[oo + OSTR]          = s0v + bz.x;
                O[oo + OSTR + 16384]  = s1v + bz.y;
            }
            oo += 2 * OSTR;
        }

        rb  = (rb  == 8) ? 0 : rb  + 4;
        rb2 = (rb2 == 8) ? 0 : rb2 + 4;
    }
}

extern "C" void kernel_launch(void* const* d_in, const int* in_sizes, int n_in,
                              void* d_out, int out_size)
{
    const float* X = (const float*)d_in[0];   // x        (64,4,2,256,256)
    const float* W = (const float*)d_in[1];   // tensors  (4,4,128,128,2,2,2,2,2)
    const float* B = (const float*)d_in[2];   // bias     (4,128,128,2)
    float* O = (float*)d_out;                 // out      (64,4,2,128,128)
    (void)in_sizes; (void)n_in; (void)out_size;
    ttn_kernel<<<128 * 16, 128>>>(X, W, B, O);
}